// round 16
// baseline (speedup 1.0000x reference)
#include <cuda_runtime.h>
#include <cstdint>

// ---------------------------------------------------------------------------
// QuantumRNNCell fused persistent kernel, v16 (sim-prologue + pure stream):
//   out[b,h] = hx[b,h] + sum_j q[b,j] * fc_w[h,j] + fc_b[h]
// Block = 256 threads, 3 CTAs/SM. Two phases per persistent CTA:
//   PROLOGUE: all 8 warps sim ALL of this CTA's tiles (packed 2 rows/warp,
//             analytic product-state encoding) into smem sq. ~5 passes.
//   ONE __syncthreads.
//   STREAM:   all 8 warps free-run a pure loop: 8 front-batched LDG.128 ->
//             q LDS.128 -> f32x2 FMA -> STG.128. No sync, no mbarrier.
// 24 streaming warps/SM (vs 16 before) attacks the latency-bound regime the
// R15 roofline revealed (nothing saturated).
// ---------------------------------------------------------------------------

#define NQ 6
#define NLAYERS 3
#define HDIM 1024
#define TR 8
#define NTHREADS 256
#define SQROW 16                 // floats per sq row (12 used, padded)
#define MAXITER 12               // max tiles per CTA (grid chosen to ensure)

// ---- packed f32x2 helpers ---------------------------------------------------
__device__ __forceinline__ uint64_t pk2(float lo, float hi) {
    uint64_t r;
    asm("mov.b64 %0, {%1, %2};" : "=l"(r) : "f"(lo), "f"(hi));
    return r;
}
__device__ __forceinline__ uint64_t ffma2(uint64_t a, uint64_t b, uint64_t c) {
    uint64_t d;
    asm("fma.rn.f32x2 %0, %1, %2, %3;" : "=l"(d) : "l"(a), "l"(b), "l"(c));
    return d;
}
__device__ __forceinline__ uint64_t fadd2(uint64_t a, uint64_t b) {
    uint64_t d;
    asm("add.rn.f32x2 %0, %1, %2;" : "=l"(d) : "l"(a), "l"(b));
    return d;
}

// ---- packed (2-row) gate helpers (validated R4..R15) -----------------------
// a[8] = {re,im} x hi2(0..3); hi2 bit1 = state bit5, hi2 bit0 = state bit4.
// State bits 3..0 = lane16 bits 3..0.
__device__ __forceinline__ void ry_pair(float a[8], int i0, int i1, float c, float s) {
    float re0 = a[2*i0], im0 = a[2*i0+1], re1 = a[2*i1], im1 = a[2*i1+1];
    a[2*i0]   = c*re0 - s*re1;
    a[2*i0+1] = c*im0 - s*im1;
    a[2*i1]   = s*re0 + c*re1;
    a[2*i1+1] = s*im0 + c*im1;
}
__device__ __forceinline__ void ry_shfl(float a[8], int m, float c, float s, unsigned lane) {
    float sg = (lane & (unsigned)m) ? s : -s;
#pragma unroll
    for (int k = 0; k < 4; k++) {
        float orr = __shfl_xor_sync(0xFFFFFFFFu, a[2*k],   m);
        float oii = __shfl_xor_sync(0xFFFFFFFFu, a[2*k+1], m);
        a[2*k]   = c*a[2*k]   + sg*orr;
        a[2*k+1] = c*a[2*k+1] + sg*oii;
    }
}
__device__ __forceinline__ void apply_ry(int w, float a[8], float c, float s, unsigned lane) {
    if (w == 0)      { ry_pair(a, 0, 2, c, s); ry_pair(a, 1, 3, c, s); }
    else if (w == 1) { ry_pair(a, 0, 1, c, s); ry_pair(a, 2, 3, c, s); }
    else             ry_shfl(a, 1 << (5 - w), c, s, lane);
}

__device__ __forceinline__ void apply_cnot_ring(int q, float a[8], unsigned lane) {
    if (q == 0) {
        float t;
        t = a[4]; a[4] = a[6]; a[6] = t;
        t = a[5]; a[5] = a[7]; a[7] = t;
    } else if (q == 1) {
#pragma unroll
        for (int k = 1; k < 4; k += 2) {
            a[2*k]   = __shfl_xor_sync(0xFFFFFFFFu, a[2*k],   8);
            a[2*k+1] = __shfl_xor_sync(0xFFFFFFFFu, a[2*k+1], 8);
        }
    } else if (q == 5) {
        if (lane & 1u) {
            float t;
            t = a[0]; a[0] = a[4]; a[4] = t;
            t = a[1]; a[1] = a[5]; a[5] = t;
            t = a[2]; a[2] = a[6]; a[6] = t;
            t = a[3]; a[3] = a[7]; a[7] = t;
        }
    } else {
        int cb = 1 << (5 - q);
        int tm = 1 << (4 - q);
        bool ctrl = (lane & (unsigned)cb) != 0;
#pragma unroll
        for (int k = 0; k < 4; k++) {
            float vr = __shfl_xor_sync(0xFFFFFFFFu, a[2*k],   tm);
            float vi = __shfl_xor_sync(0xFFFFFFFFu, a[2*k+1], tm);
            if (ctrl) { a[2*k] = vr; a[2*k+1] = vi; }
        }
    }
}

// ---- full sim for one row (16-lane half-warp); q written duplicated --------
__device__ __forceinline__ void sim_rows(
    const float* __restrict__ x, const float* swc, const float* sws,
    float* sqdst, int trow, int b, unsigned lane, unsigned lane16) {
    float cx[NQ], sx[NQ];
#pragma unroll
    for (int j = 0; j < NQ; j++) {
        __sincosf(__ldg(&x[b * NQ + j]) * 0.5f, &sx[j], &cx[j]);
    }

    // per-wire v = RZ*RY*RX|0>
    float v0r[NQ], v0i[NQ], v1r[NQ], v1i[NQ];
#pragma unroll
    for (int iw = 0; iw < NQ; iw++) {
        int j1 = (iw + 1 > 5) ? iw - 5 : iw + 1;
        int j2 = (iw + 2 > 5) ? iw - 4 : iw + 2;
        float ar = cx[j1] * cx[iw];
        float ai = sx[j1] * sx[iw];
        float br = sx[j1] * cx[iw];
        float bi = -cx[j1] * sx[iw];
        float cz = cx[j2], sz = sx[j2];
        v0r[iw] = ar * cz + ai * sz;
        v0i[iw] = ai * cz - ar * sz;
        v1r[iw] = br * cz - bi * sz;
        v1i[iw] = bi * cz + br * sz;
    }

    // f = prod over wires 2..5; wire w bit = lane16 bit (5-w)
    float fr, fi;
    {
        bool bs = (lane16 & 8u) != 0;
        fr = bs ? v1r[2] : v0r[2];
        fi = bs ? v1i[2] : v0i[2];
    }
#pragma unroll
    for (int w2 = 3; w2 <= 5; w2++) {
        bool bs = (lane16 & (1u << (5 - w2))) != 0;
        float tr = bs ? v1r[w2] : v0r[w2];
        float ti = bs ? v1i[w2] : v0i[w2];
        float nr = fr * tr - fi * ti;
        float ni = fr * ti + fi * tr;
        fr = nr; fi = ni;
    }

    float a[8];
#pragma unroll
    for (int k = 0; k < 4; k++) {
        float u0r = (k & 2) ? v1r[0] : v0r[0];
        float u0i = (k & 2) ? v1i[0] : v0i[0];
        float u1r = (k & 1) ? v1r[1] : v0r[1];
        float u1i = (k & 1) ? v1i[1] : v0i[1];
        float gr = u0r * u1r - u0i * u1i;
        float gi = u0r * u1i + u0i * u1r;
        a[2*k]   = gr * fr - gi * fi;
        a[2*k+1] = gr * fi + gi * fr;
    }

#pragma unroll
    for (int l = 0; l < NLAYERS; l++) {
#pragma unroll
        for (int q = 0; q < NQ; q++)
            apply_ry(q, a, swc[l * NQ + q], sws[l * NQ + q], lane);
#pragma unroll
        for (int q = 0; q < NQ; q++) apply_cnot_ring(q, a, lane);
    }

    float p0 = a[0]*a[0] + a[1]*a[1];
    float p1 = a[2]*a[2] + a[3]*a[3];
    float p2 = a[4]*a[4] + a[5]*a[5];
    float p3 = a[6]*a[6] + a[7]*a[7];
    float ptot = p0 + p1 + p2 + p3;

    float e[NQ];
    e[0] = (p0 + p1) - (p2 + p3);
    e[1] = (p0 - p1) + (p2 - p3);
#pragma unroll
    for (int j = 2; j < NQ; j++) {
        float sg = (lane16 & (unsigned)(1 << (5 - j))) ? -1.0f : 1.0f;
        e[j] = sg * ptot;
    }
#pragma unroll
    for (int off = 8; off; off >>= 1) {
#pragma unroll
        for (int j = 0; j < NQ; j++)
            e[j] += __shfl_xor_sync(0xFFFFFFFFu, e[j], off);
    }
    if (lane16 == 0) {
#pragma unroll
        for (int j = 0; j < NQ; j++) {
            sqdst[trow * SQROW + 2 * j]     = e[j];
            sqdst[trow * SQROW + 2 * j + 1] = e[j];
        }
    }
}

// ---- fused persistent kernel ------------------------------------------------
__global__ __launch_bounds__(NTHREADS, 3)
void fused_kernel(const float* __restrict__ x,
                  const float* __restrict__ hx,
                  const float* __restrict__ qw,    // (3,6)
                  const float* __restrict__ fc_w,  // (1024,6)
                  const float* __restrict__ fc_b,  // (1024,)
                  float* __restrict__ out,
                  int B, int ntiles) {
    __shared__ float sq[MAXITER * TR * SQROW];   // 6 KB
    __shared__ float swc[NLAYERS * NQ];
    __shared__ float sws[NLAYERS * NQ];

    const int tid = threadIdx.x;
    const int warp = tid >> 5;
    const unsigned lane = tid & 31u;
    const unsigned lane16 = lane & 15u;
    const int half = (int)(lane >> 4);
    const int stride = gridDim.x;
    const int t0 = blockIdx.x;

    // ---- fc weights + bias as packed f32x2 registers (all threads) ----
    const int h0 = 4 * tid;
    uint64_t w0l = pk2(__ldg(&fc_w[(h0+0)*NQ+0]), __ldg(&fc_w[(h0+1)*NQ+0]));
    uint64_t w0h = pk2(__ldg(&fc_w[(h0+2)*NQ+0]), __ldg(&fc_w[(h0+3)*NQ+0]));
    uint64_t w1l = pk2(__ldg(&fc_w[(h0+0)*NQ+1]), __ldg(&fc_w[(h0+1)*NQ+1]));
    uint64_t w1h = pk2(__ldg(&fc_w[(h0+2)*NQ+1]), __ldg(&fc_w[(h0+3)*NQ+1]));
    uint64_t w2l = pk2(__ldg(&fc_w[(h0+0)*NQ+2]), __ldg(&fc_w[(h0+1)*NQ+2]));
    uint64_t w2h = pk2(__ldg(&fc_w[(h0+2)*NQ+2]), __ldg(&fc_w[(h0+3)*NQ+2]));
    uint64_t w3l = pk2(__ldg(&fc_w[(h0+0)*NQ+3]), __ldg(&fc_w[(h0+1)*NQ+3]));
    uint64_t w3h = pk2(__ldg(&fc_w[(h0+2)*NQ+3]), __ldg(&fc_w[(h0+3)*NQ+3]));
    uint64_t w4l = pk2(__ldg(&fc_w[(h0+0)*NQ+4]), __ldg(&fc_w[(h0+1)*NQ+4]));
    uint64_t w4h = pk2(__ldg(&fc_w[(h0+2)*NQ+4]), __ldg(&fc_w[(h0+3)*NQ+4]));
    uint64_t w5l = pk2(__ldg(&fc_w[(h0+0)*NQ+5]), __ldg(&fc_w[(h0+1)*NQ+5]));
    uint64_t w5h = pk2(__ldg(&fc_w[(h0+2)*NQ+5]), __ldg(&fc_w[(h0+3)*NQ+5]));
    uint64_t bvl = pk2(__ldg(&fc_b[h0+0]), __ldg(&fc_b[h0+1]));
    uint64_t bvh = pk2(__ldg(&fc_b[h0+2]), __ldg(&fc_b[h0+3]));

    if (tid < NLAYERS * NQ) {
        float s, c;
        __sincosf(__ldg(&qw[tid]) * 0.5f, &s, &c);
        swc[tid] = c; sws[tid] = s;
    }
    __syncthreads();   // swc/sws visible for the sim prologue

    // ---- number of tiles this CTA owns ----
    int niter = 0;
    if (t0 < ntiles) niter = (ntiles - t0 + stride - 1) / stride;

    // ---- PROLOGUE: sim all rows of this CTA's tiles into sq ----
    {
        const int nrows = niter * TR;
        for (int L = warp * 2 + half; L < nrows; L += 16) {
            int itt = L >> 3;            // tile index (local)
            int r = L & 7;               // row within tile
            int b = (t0 + itt * stride) * TR + r;
            if (b >= B) b = B - 1;
            sim_rows(x, swc, sws, sq, L, b, lane, lane16);
        }
    }
    __syncthreads();   // sq complete

    // ---- STREAM: pure free-running loop, no synchronization ----
    int it2 = 0;
    for (int t = t0; t < ntiles; t += stride, it2++) {
        const int row0 = t * TR;

        // front-batched direct loads: 8 x LDG.128 (MLP = 8)
        uint64_t hl[TR], hh[TR];
#pragma unroll
        for (int r = 0; r < TR; r++) {
            int gb = min(row0 + r, B - 1);
            const float* src = hx + (size_t)gb * HDIM + 4 * tid;
            asm volatile("ld.global.cs.v2.u64 {%0, %1}, [%2];"
                         : "=l"(hl[r]), "=l"(hh[r]) : "l"(src));
        }

        const float* sqr = &sq[it2 * (TR * SQROW)];
#pragma unroll
        for (int r = 0; r < TR; r++) {
            int b = row0 + r;
            if (b >= B) break;
            const float* qr = &sqr[r * SQROW];
            ulonglong2 q01 = *(const ulonglong2*)&qr[0];
            ulonglong2 q23 = *(const ulonglong2*)&qr[4];
            ulonglong2 q45 = *(const ulonglong2*)&qr[8];

            uint64_t lo = ffma2(q01.x, w0l, bvl);
            uint64_t hi = ffma2(q01.x, w0h, bvh);
            lo = ffma2(q01.y, w1l, lo);  hi = ffma2(q01.y, w1h, hi);
            lo = ffma2(q23.x, w2l, lo);  hi = ffma2(q23.x, w2h, hi);
            lo = ffma2(q23.y, w3l, lo);  hi = ffma2(q23.y, w3h, hi);
            lo = ffma2(q45.x, w4l, lo);  hi = ffma2(q45.x, w4h, hi);
            lo = ffma2(q45.y, w5l, lo);  hi = ffma2(q45.y, w5h, hi);
            lo = fadd2(lo, hl[r]);
            hi = fadd2(hi, hh[r]);

            float* dst = out + (size_t)b * HDIM + 4 * tid;
            asm volatile("st.global.cs.v2.b64 [%0], {%1, %2};"
                         :: "l"(dst), "l"(lo), "l"(hi) : "memory");
        }
    }
}

// ---- launch ----------------------------------------------------------------
extern "C" void kernel_launch(void* const* d_in, const int* in_sizes, int n_in,
                              void* d_out, int out_size) {
    const float* x    = (const float*)d_in[0];   // (B,6)
    const float* hx   = (const float*)d_in[1];   // (B,1024)
    const float* qw   = (const float*)d_in[2];   // (3,6)
    const float* fc_w = (const float*)d_in[3];   // (1024,6)
    const float* fc_b = (const float*)d_in[4];   // (1024,)
    float* out = (float*)d_out;

    int B = in_sizes[0] / NQ;
    int ntiles = (B + TR - 1) / TR;

    int grid = 148 * 3;                        // 3 CTAs/SM persistent
    if (grid > ntiles) grid = ntiles;
    // ensure niter <= MAXITER
    int min_grid = (ntiles + MAXITER - 1) / MAXITER;
    if (grid < min_grid) grid = min_grid;

    fused_kernel<<<grid, NTHREADS>>>(x, hx, qw, fc_w, fc_b, out, B, ntiles);
}